// round 7
// baseline (speedup 1.0000x reference)
#include <cuda_runtime.h>
#include <cstdint>
#include <cstddef>

#define T_LEN 1000
#define B_SZ  512
#define C_IN  22
#define H_SZ  64
#define TH    (T_LEN * H_SZ)  // 64000

typedef unsigned long long ull;

// xproj layout: ull index = ((t*128 + cta)*256 + col)*2 + pair
// value lanes = (row 4*cta+2*pair, row 4*cta+2*pair+1), bias included.
__device__ ull   g_xproj[(size_t)T_LEN * 128 * 512];
__device__ float g_wfcT[TH * 4];   // [t*64+u][class]

__device__ __forceinline__ ull pack2f(float lo, float hi) {
    ull r;
    uint32_t a = __float_as_uint(lo), b = __float_as_uint(hi);
    asm("mov.b64 %0, {%1, %2};" : "=l"(r) : "r"(a), "r"(b));
    return r;
}
__device__ __forceinline__ ull splat2(float w) {
    ull r;
    uint32_t u = __float_as_uint(w);
    asm("mov.b64 %0, {%1, %1};" : "=l"(r) : "r"(u));
    return r;
}
__device__ __forceinline__ void ffma2(ull& d, ull a, ull b) {
    asm("fma.rn.f32x2 %0, %1, %2, %3;" : "=l"(d) : "l"(a), "l"(b), "l"(d));
}
__device__ __forceinline__ void unpack2(ull v, float& lo, float& hi) {
    uint32_t ulo, uhi;
    asm("mov.b64 {%0, %1}, %2;" : "=r"(ulo), "=r"(uhi) : "l"(v));
    lo = __uint_as_float(ulo);
    hi = __uint_as_float(uhi);
}
__device__ __forceinline__ float tanh_fast(float x) {
    float y;
    asm("tanh.approx.f32 %0, %1;" : "=f"(y) : "f"(x));
    return y;
}

// ---------------------------------------------------------------------------
// Kernel A: x_proj precompute. Block = 128 threads (thread = cols 2j, 2j+1),
// grid = (128 cta-groups of 4 rows, 16 t-tiles of 64).
// Row-pair packed accumulators -> gate-x values stored directly (incl. bias).
// ---------------------------------------------------------------------------
__global__ void __launch_bounds__(128) xproj_kernel(
    const float* __restrict__ x, const float* __restrict__ W_ih,
    const float* __restrict__ b_ih, const float* __restrict__ b_hh)
{
    __shared__ __align__(16) ull xsP[2][C_IN][64];   // [pair][ch][tt], lanes=rows

    const int j   = threadIdx.x;          // 0..127
    const int cta = blockIdx.x;           // 0..127 (rows 4cta..4cta+3)
    const int t0  = blockIdx.y * 64;
    const int tlen = (t0 + 64 <= T_LEN) ? 64 : (T_LEN - t0);

    // stage x: 4 rows x 22 ch x 64 tt
    for (int idx = j; idx < 4 * C_IN * 64; idx += 128) {
        int rr  = idx / (C_IN * 64);
        int rem = idx - rr * (C_IN * 64);
        int c   = rem >> 6;
        int tt  = rem & 63;
        float v = (tt < tlen)
            ? x[(size_t)(4 * cta + rr) * C_IN * T_LEN + c * T_LEN + t0 + tt] : 0.f;
        ((float*)&xsP[rr >> 1][c][tt])[rr & 1] = v;
    }

    // splat weights for cols c0=2j, c1=2j+1 (once)
    const int c0 = 2 * j, c1 = 2 * j + 1;
    ull w0[C_IN], w1[C_IN];
#pragma unroll
    for (int c = 0; c < C_IN; c++) {
        w0[c] = splat2(W_ih[c0 * C_IN + c]);
        w1[c] = splat2(W_ih[c1 * C_IN + c]);
    }
    const ull bias0 = splat2(b_ih[c0] + b_hh[c0]);
    const ull bias1 = splat2(b_ih[c1] + b_hh[c1]);
    __syncthreads();

    // process 2 timesteps per iteration (LDS.128 x reads)
    for (int i = 0; i < tlen; i += 2) {
        ull a00a = bias0, a00b = bias0;   // col0 pair0, tt i / i+1
        ull a01a = bias0, a01b = bias0;   // col0 pair1
        ull a10a = bias1, a10b = bias1;   // col1 pair0
        ull a11a = bias1, a11b = bias1;   // col1 pair1
#pragma unroll
        for (int c = 0; c < C_IN; c++) {
            ulonglong2 xA = *(const ulonglong2*)&xsP[0][c][i];
            ulonglong2 xB = *(const ulonglong2*)&xsP[1][c][i];
            ffma2(a00a, w0[c], xA.x); ffma2(a00b, w0[c], xA.y);
            ffma2(a01a, w0[c], xB.x); ffma2(a01b, w0[c], xB.y);
            ffma2(a10a, w1[c], xA.x); ffma2(a10b, w1[c], xA.y);
            ffma2(a11a, w1[c], xB.x); ffma2(a11b, w1[c], xB.y);
        }
        // store: ull idx = ((t*128+cta)*256 + col)*2 + pair
        size_t base0 = ((size_t)(t0 + i)     * 128 + cta) * 512 + 4 * j;
        size_t base1 = ((size_t)(t0 + i + 1) * 128 + cta) * 512 + 4 * j;
        *(ulonglong2*)&g_xproj[base0]     = make_ulonglong2(a00a, a01a);
        *(ulonglong2*)&g_xproj[base0 + 2] = make_ulonglong2(a10a, a11a);
        *(ulonglong2*)&g_xproj[base1]     = make_ulonglong2(a00b, a01b);
        *(ulonglong2*)&g_xproj[base1 + 2] = make_ulonglong2(a10b, a11b);
    }
}

// ---------------------------------------------------------------------------
// Kernel B: W_fc -> [t*64+u][4] float4
// ---------------------------------------------------------------------------
__global__ void wfcT_kernel(const float* __restrict__ W_fc) {
    int i = blockIdx.x * 256 + threadIdx.x;
    if (i < TH) {
        float4 v;
        v.x = W_fc[i];
        v.y = W_fc[TH + i];
        v.z = W_fc[2 * TH + i];
        v.w = W_fc[3 * TH + i];
        ((float4*)g_wfcT)[i] = v;
    }
}

// ---------------------------------------------------------------------------
// Kernel C: fused LSTM recurrence + FC + softmax.
// grid = 128 CTAs (4 rows each = pairs P0, P1), block = 256.
// Thread j: pair p=j>>7, columns jc=j&127 and jc+128 (h read once, used twice).
// ---------------------------------------------------------------------------
__global__ void __launch_bounds__(256, 1) lstm_fused(
    const float* __restrict__ W_hh, const float* __restrict__ b_fc,
    float* __restrict__ out)
{
    __shared__ __align__(16) ull hRow[4][32];   // hidden-pair packed, per row
    __shared__ __align__(16) ull g2[2][256];    // [pair][col], lanes = rows
    __shared__ float red[16 * 64];
    __shared__ float logits_sh[4][4];

    const int j   = threadIdx.x;
    const int cta = blockIdx.x;
    const int p   = j >> 7;        // pair handled in phase A
    const int jc  = j & 127;
    const int c0  = jc, c1 = jc + 128;

    // pack W_hh rows c0, c1 (hidden-pair)
    ull whh0[32], whh1[32];
    {
        const float4* wp0 = reinterpret_cast<const float4*>(W_hh + c0 * H_SZ);
        const float4* wp1 = reinterpret_cast<const float4*>(W_hh + c1 * H_SZ);
#pragma unroll
        for (int k = 0; k < 16; k++) {
            float4 v0 = wp0[k], v1 = wp1[k];
            whh0[2*k]   = pack2f(v0.x, v0.y);
            whh0[2*k+1] = pack2f(v0.z, v0.w);
            whh1[2*k]   = pack2f(v1.x, v1.y);
            whh1[2*k+1] = pack2f(v1.z, v1.w);
        }
    }

    // nonlinearity: c0 in 0..127 (i/f gates) = sigmoid always.
    // c1 in 128..255: g-gate (tanh) if jc<64 else o-gate (sigmoid).
    const bool  c1_is_g = (jc < 64);
    const float n1_pre = c1_is_g ? 1.f : 0.5f;
    const float n1_sc  = c1_is_g ? 1.f : 0.5f;
    const float n1_off = c1_is_g ? 0.f : 0.5f;

    if (j < 128) hRow[j >> 5][j & 31] = 0ull;

    // phase-B state threads: j<128, unit u, pair pb; rows 2pb, 2pb+1
    const int u  = j & 63;
    const int pb = j >> 6;
    float cA = 0.f, cB = 0.f;
    float pA0 = 0.f, pA1 = 0.f, pA2 = 0.f, pA3 = 0.f;
    float pB0 = 0.f, pB1 = 0.f, pB2 = 0.f, pB3 = 0.f;
    float4 wf = make_float4(0.f, 0.f, 0.f, 0.f);
    if (j < 128) wf = ((const float4*)g_wfcT)[u];

    // xproj prefetch (t=0): (col, p) at ull idx (t*128+cta)*512 + col*2 + p
    const ull* xq = g_xproj + (size_t)cta * 512 + p;
    ull xv0 = xq[c0 * 2];
    ull xv1 = xq[c1 * 2];
    __syncthreads();

    for (int t = 0; t < T_LEN; t++) {
        // ---- phase A: gates for (cols c0,c1) x (rows of pair p) ----
        ull a00 = 0ull, a01 = 0ull, a10 = 0ull, a11 = 0ull;
        const ulonglong2* hA2 = reinterpret_cast<const ulonglong2*>(hRow[2*p]);
        const ulonglong2* hB2 = reinterpret_cast<const ulonglong2*>(hRow[2*p+1]);
#pragma unroll
        for (int k = 0; k < 16; k++) {
            ulonglong2 hA = hA2[k];
            ulonglong2 hB = hB2[k];
            ffma2(a00, whh0[2*k],   hA.x);
            ffma2(a01, whh0[2*k],   hB.x);
            ffma2(a10, whh1[2*k],   hA.x);
            ffma2(a11, whh1[2*k],   hB.x);
            ffma2(a00, whh0[2*k+1], hA.y);
            ffma2(a01, whh0[2*k+1], hB.y);
            ffma2(a10, whh1[2*k+1], hA.y);
            ffma2(a11, whh1[2*k+1], hB.y);
        }

        // prefetch xproj(t+1)
        ull xn0 = xv0, xn1 = xv1;
        if (t + 1 < T_LEN) {
            const ull* xqn = xq + (size_t)(t + 1) * 65536;
            xn0 = xqn[c0 * 2];
            xn1 = xqn[c1 * 2];
        }

        float x0A, x0B, x1A, x1B;
        unpack2(xv0, x0A, x0B);
        unpack2(xv1, x1A, x1B);
        float s, h2;
        unpack2(a00, s, h2); float v0A = s + h2 + x0A;
        unpack2(a01, s, h2); float v0B = s + h2 + x0B;
        unpack2(a10, s, h2); float v1A = s + h2 + x1A;
        unpack2(a11, s, h2); float v1B = s + h2 + x1B;

        // col0: sigmoid; col1: tanh or sigmoid
        float n0A = fmaf(0.5f, tanh_fast(0.5f * v0A), 0.5f);
        float n0B = fmaf(0.5f, tanh_fast(0.5f * v0B), 0.5f);
        float n1A = fmaf(n1_sc, tanh_fast(n1_pre * v1A), n1_off);
        float n1B = fmaf(n1_sc, tanh_fast(n1_pre * v1B), n1_off);
        g2[p][c0] = pack2f(n0A, n0B);
        g2[p][c1] = pack2f(n1A, n1B);
        xv0 = xn0; xv1 = xn1;
        __syncthreads();   // gates visible

        // ---- phase B: state update, threads 0..127 (pair pb, unit u) ----
        if (j < 128) {
            float iA, iB, fA, fB, gA, gB, oA, oB;
            unpack2(g2[pb][u],        iA, iB);
            unpack2(g2[pb][ 64 + u],  fA, fB);
            unpack2(g2[pb][128 + u],  gA, gB);
            unpack2(g2[pb][192 + u],  oA, oB);
            cA = fmaf(fA, cA, iA * gA);
            cB = fmaf(fB, cB, iB * gB);
            float hAv = oA * tanh_fast(cA);
            float hBv = oB * tanh_fast(cB);
            ((float*)&hRow[2*pb    ][u >> 1])[u & 1] = hAv;   // publish first
            ((float*)&hRow[2*pb + 1][u >> 1])[u & 1] = hBv;

            pA0 = fmaf(hAv, wf.x, pA0); pA1 = fmaf(hAv, wf.y, pA1);
            pA2 = fmaf(hAv, wf.z, pA2); pA3 = fmaf(hAv, wf.w, pA3);
            pB0 = fmaf(hBv, wf.x, pB0); pB1 = fmaf(hBv, wf.y, pB1);
            pB2 = fmaf(hBv, wf.z, pB2); pB3 = fmaf(hBv, wf.w, pB3);
            int tn = (t + 1 < T_LEN) ? t + 1 : t;
            wf = ((const float4*)g_wfcT)[tn * H_SZ + u];
        }
        __syncthreads();   // h(t) visible
    }

    // ---- FC reduction + softmax (4 rows: rg = 2*pb + {0,1}) ----
    if (j < 128) {
        int rgA = 2 * pb, rgB = 2 * pb + 1;
        red[(rgA * 4 + 0) * 64 + u] = pA0;
        red[(rgA * 4 + 1) * 64 + u] = pA1;
        red[(rgA * 4 + 2) * 64 + u] = pA2;
        red[(rgA * 4 + 3) * 64 + u] = pA3;
        red[(rgB * 4 + 0) * 64 + u] = pB0;
        red[(rgB * 4 + 1) * 64 + u] = pB1;
        red[(rgB * 4 + 2) * 64 + u] = pB2;
        red[(rgB * 4 + 3) * 64 + u] = pB3;
    }
    __syncthreads();
    if (j < 16) {
        int rr = j >> 2, nn = j & 3;
        float sum = 0.f;
#pragma unroll
        for (int k = 0; k < 64; k++) sum += red[(rr * 4 + nn) * 64 + k];
        logits_sh[rr][nn] = sum + b_fc[nn];
    }
    __syncthreads();
    if (j < 4) {
        float l0 = logits_sh[j][0], l1 = logits_sh[j][1];
        float l2 = logits_sh[j][2], l3 = logits_sh[j][3];
        float m  = fmaxf(fmaxf(l0, l1), fmaxf(l2, l3));
        float q0 = __expf(l0 - m), q1 = __expf(l1 - m);
        float q2 = __expf(l2 - m), q3 = __expf(l3 - m);
        float inv = 1.f / (q0 + q1 + q2 + q3);
        float* o = out + (4 * cta + j) * 4;
        o[0] = q0 * inv; o[1] = q1 * inv; o[2] = q2 * inv; o[3] = q3 * inv;
    }
}

// ---------------------------------------------------------------------------
extern "C" void kernel_launch(void* const* d_in, const int* in_sizes, int n_in,
                              void* d_out, int out_size) {
    const float* x    = (const float*)d_in[0];
    const float* W_ih = (const float*)d_in[1];
    const float* W_hh = (const float*)d_in[2];
    const float* b_ih = (const float*)d_in[3];
    const float* b_hh = (const float*)d_in[4];
    const float* W_fc = (const float*)d_in[5];
    const float* b_fc = (const float*)d_in[6];
    float* out = (float*)d_out;

    xproj_kernel<<<dim3(128, 16), 128>>>(x, W_ih, b_ih, b_hh);
    wfcT_kernel<<<(TH + 255) / 256, 256>>>(W_fc);
    lstm_fused<<<128, 256>>>(W_hh, b_fc, out);
}